// round 3
// baseline (speedup 1.0000x reference)
#include <cuda_runtime.h>
#include <math.h>

// Problem constants
#define BB   4
#define NN1  16384
#define NN2  4096
#define CC   128
#define KIN  384      // 3*C
#define MOUT 256      // MLP width (both layers)
#define TN   64       // points per block tile in main kernel
#define SX   65       // padded smem row stride (floats) -> conflict-free column stores

// ---------------- device scratch (no allocations allowed) ----------------
__device__ float g_w0f[MOUT * KIN];    // BN-folded weights layer 0
__device__ float g_b0f[MOUT];
__device__ float g_w1f[MOUT * MOUT];   // BN-folded weights layer 1
__device__ float g_b1f[MOUT];
__device__ float g_p2t[BB * NN2 * CC]; // transposed points2: (B, N2, C)
__device__ int   g_i3[BB * NN1 * 3];   // 3-NN indices
__device__ float g_wt3[BB * NN1 * 3];  // normalized inverse-distance weights

// ---------------- BN fold: w' = w * g*rsqrt(v+eps), b' = (b-m)*s + beta ---
__global__ void fold_kernel(const float* __restrict__ w, const float* __restrict__ b,
                            const float* __restrict__ g, const float* __restrict__ beta,
                            const float* __restrict__ m, const float* __restrict__ v,
                            int layer)
{
    const int K = (layer == 0) ? KIN : MOUT;
    float* wf = (layer == 0) ? g_w0f : g_w1f;
    float* bf = (layer == 0) ? g_b0f : g_b1f;
    int idx = blockIdx.x * blockDim.x + threadIdx.x;
    if (idx < MOUT * K) {
        int o = idx / K;
        float s = g[o] * rsqrtf(v[o] + 1e-5f);
        wf[idx] = w[idx] * s;
    }
    if (idx < MOUT) {
        float s = g[idx] * rsqrtf(v[idx] + 1e-5f);
        bf[idx] = (b[idx] - m[idx]) * s + beta[idx];
    }
}

// ---------------- transpose points2 (B,C,N2) -> (B,N2,C) ------------------
__global__ void transpose_kernel(const float* __restrict__ p2)
{
    __shared__ float tile[32][33];
    int b  = blockIdx.z;
    int n0 = blockIdx.x * 32;
    int c0 = blockIdx.y * 32;
    int tx = threadIdx.x, ty = threadIdx.y;   // block (32, 8)
    #pragma unroll
    for (int r = 0; r < 32; r += 8)
        tile[ty + r][tx] = p2[(b * CC + c0 + ty + r) * NN2 + n0 + tx];
    __syncthreads();
    #pragma unroll
    for (int r = 0; r < 32; r += 8)
        g_p2t[(b * NN2 + n0 + ty + r) * CC + c0 + tx] = tile[tx][ty + r];
}

// ---------------- 3-NN search: one thread per query point ----------------
// score = 2*q.dot(p) - |p|^2 ; argmax score == argmin squared distance.
// d = |q|^2 - score  reproduces the reference's  |q|^2 + |p|^2 - 2 q.p  form.
// Strict '>' comparisons keep the earliest index on ties (matches top_k).
__global__ void nn3_kernel(const float* __restrict__ xyz1,
                           const float* __restrict__ xyz2)
{
    extern __shared__ float4 sc[];   // NN2 float4 = 64KB
    int tid = threadIdx.x;
    int pt  = blockIdx.x * 256 + tid;
    int b   = pt >> 14;              // N1 = 16384 per batch, 256 | 16384
    const float* x2 = xyz2 + b * NN2 * 3;
    for (int j = tid; j < NN2; j += 256) {
        float x = x2[j * 3], y = x2[j * 3 + 1], z = x2[j * 3 + 2];
        sc[j] = make_float4(x, y, z, -(x * x + y * y + z * z));
    }
    __syncthreads();

    float px = xyz1[pt * 3], py = xyz1[pt * 3 + 1], pz = xyz1[pt * 3 + 2];
    float xx = px * px + py * py + pz * pz;
    float qx = px + px, qy = py + py, qz = pz + pz;

    float s0 = -INFINITY, s1 = -INFINITY, s2 = -INFINITY;
    int j0 = 0, j1 = 0, j2 = 0;
    #pragma unroll 4
    for (int j = 0; j < NN2; j++) {
        float4 f = sc[j];
        float sco = fmaf(qx, f.x, fmaf(qy, f.y, fmaf(qz, f.z, f.w)));
        if (sco > s2) {
            if (sco > s1) {
                s2 = s1; j2 = j1;
                if (sco > s0) { s1 = s0; j1 = j0; s0 = sco; j0 = j; }
                else          { s1 = sco; j1 = j; }
            } else { s2 = sco; j2 = j; }
        }
    }
    float d0 = xx - s0, d1 = xx - s1, d2 = xx - s2;   // ascending distances
    float w0 = 1.0f / d0, w1 = 1.0f / d1, w2 = 1.0f / d2;
    float inv = 1.0f / (w0 + w1 + w2);
    g_i3 [pt * 3 + 0] = j0; g_i3 [pt * 3 + 1] = j1; g_i3 [pt * 3 + 2] = j2;
    g_wt3[pt * 3 + 0] = w0 * inv;
    g_wt3[pt * 3 + 1] = w1 * inv;
    g_wt3[pt * 3 + 2] = w2 * inv;
}

// ---------------- tiled fp32 GEMM on one 256 x 64 output tile -------------
// W: (256, K) row-major in global; x: smem [K][SX]; double-buffered K-chunks
// of 16 staged through smem; each thread owns an 8x8 micro-tile.
template <int K>
__device__ __forceinline__ void gemm_tile(const float* __restrict__ Wg,
                                          const float* __restrict__ xsrc,
                                          float* __restrict__ ws,
                                          float (&acc)[8][8],
                                          int tid, int ty, int tx)
{
    const float* wrow = Wg + tid * K;   // thread tid stages output row m = tid
    float4 pf[4];
    #pragma unroll
    for (int q = 0; q < 4; q++)
        pf[q] = *reinterpret_cast<const float4*>(wrow + 4 * q);
    #pragma unroll
    for (int q = 0; q < 4; q++) {
        ws[(4 * q + 0) * 256 + tid] = pf[q].x;
        ws[(4 * q + 1) * 256 + tid] = pf[q].y;
        ws[(4 * q + 2) * 256 + tid] = pf[q].z;
        ws[(4 * q + 3) * 256 + tid] = pf[q].w;
    }
    __syncthreads();

    #pragma unroll 1
    for (int kc = 0; kc < K; kc += 16) {
        const float* wbuf = ws + ((kc >> 4) & 1) * 4096;
        const bool more = (kc + 16) < K;
        if (more) {
            #pragma unroll
            for (int q = 0; q < 4; q++)
                pf[q] = *reinterpret_cast<const float4*>(wrow + kc + 16 + 4 * q);
        }
        #pragma unroll 4
        for (int s = 0; s < 16; s++) {
            float xr[8], wr[8];
            const float* xrow = xsrc + (kc + s) * SX + tx * 8;
            const float* wsr  = wbuf + s * 256 + ty * 8;
            #pragma unroll
            for (int j = 0; j < 8; j++) xr[j] = xrow[j];
            #pragma unroll
            for (int i = 0; i < 8; i++) wr[i] = wsr[i];
            #pragma unroll
            for (int i = 0; i < 8; i++)
                #pragma unroll
                for (int j = 0; j < 8; j++)
                    acc[i][j] = fmaf(wr[i], xr[j], acc[i][j]);
        }
        if (more) {
            float* nbuf = ws + (((kc >> 4) + 1) & 1) * 4096;
            #pragma unroll
            for (int q = 0; q < 4; q++) {
                nbuf[(4 * q + 0) * 256 + tid] = pf[q].x;
                nbuf[(4 * q + 1) * 256 + tid] = pf[q].y;
                nbuf[(4 * q + 2) * 256 + tid] = pf[q].z;
                nbuf[(4 * q + 3) * 256 + tid] = pf[q].w;
            }
        }
        __syncthreads();
    }
}

// ---------------- fused: interp-gather + concat + MLP x2 + channel max ----
// smem: xs[384][SX] (layer-1 input aliases rows 0..255 afterwards),
//       ws 2x16x256 weight stages, pm[32][64] partial maxes.
__global__ void __launch_bounds__(256, 1)
fp_main_kernel(const float* __restrict__ points1,
               const float* __restrict__ pointsb1,
               float* __restrict__ out)
{
    extern __shared__ float smem[];
    float* xs = smem;                       // KIN * SX floats
    float* ws = smem + KIN * SX;            // 8192 floats
    float* pm = ws + 8192;                  // 32 * TN floats

    const int tid = threadIdx.x;
    const int ty = tid >> 3, tx = tid & 7;
    const int blk = blockIdx.x;
    const int b = blk >> 8;                 // 256 tiles per batch
    const int n1base = (blk & 255) * TN;

    // --- build x tile: rows 0..127 points1, 128..255 fused, 256..383 points_b1
    const float* p1 = points1  + (b * CC) * NN1 + n1base;
    const float* pb = pointsb1 + (b * CC) * NN1 + n1base;
    for (int i = tid; i < CC * TN; i += 256) {
        int c = i >> 6, n = i & 63;
        xs[c * SX + n]          = p1[c * NN1 + n];
        xs[(256 + c) * SX + n]  = pb[c * NN1 + n];
    }
    {
        int warp = tid >> 5, lane = tid & 31;
        const float* p2b = g_p2t + b * NN2 * CC;
        #pragma unroll 1
        for (int j = 0; j < 8; j++) {
            int n  = warp * 8 + j;
            int pt = b * NN1 + n1base + n;
            int i0 = g_i3[pt * 3], i1 = g_i3[pt * 3 + 1], i2 = g_i3[pt * 3 + 2];
            float w0 = g_wt3[pt * 3], w1 = g_wt3[pt * 3 + 1], w2 = g_wt3[pt * 3 + 2];
            const float* r0 = p2b + i0 * CC;
            const float* r1 = p2b + i1 * CC;
            const float* r2 = p2b + i2 * CC;
            #pragma unroll
            for (int t = 0; t < 4; t++) {
                int c = lane + 32 * t;
                float v = w0 * r0[c] + w1 * r1[c] + w2 * r2[c];
                xs[(128 + c) * SX + n] = v;   // SX=65 -> conflict-free column store
            }
        }
    }
    __syncthreads();

    float acc[8][8];
    #pragma unroll
    for (int i = 0; i < 8; i++)
        #pragma unroll
        for (int j = 0; j < 8; j++) acc[i][j] = 0.0f;

    // layer 0: y1 = relu(W0f @ x + b0f)
    gemm_tile<KIN>(g_w0f, xs, ws, acc, tid, ty, tx);

    #pragma unroll
    for (int i = 0; i < 8; i++) {
        float bb = g_b0f[ty * 8 + i];
        #pragma unroll
        for (int j = 0; j < 8; j++) {
            xs[(ty * 8 + i) * SX + tx * 8 + j] = fmaxf(acc[i][j] + bb, 0.0f);
            acc[i][j] = 0.0f;
        }
    }
    __syncthreads();

    // layer 1: y2 = relu(W1f @ y1 + b1f); fold relu into final max (>= 0)
    gemm_tile<MOUT>(g_w1f, xs, ws, acc, tid, ty, tx);

    #pragma unroll
    for (int j = 0; j < 8; j++) {
        float mv = -INFINITY;
        #pragma unroll
        for (int i = 0; i < 8; i++)
            mv = fmaxf(mv, acc[i][j] + g_b1f[ty * 8 + i]);
        pm[ty * TN + tx * 8 + j] = mv;
    }
    __syncthreads();

    if (tid < TN) {
        float mv = 0.0f;   // relu floor
        #pragma unroll
        for (int t = 0; t < 32; t++)
            mv = fmaxf(mv, pm[t * TN + tid]);
        out[b * NN1 + n1base + tid] = mv;
    }
}

// ---------------- launch --------------------------------------------------
extern "C" void kernel_launch(void* const* d_in, const int* in_sizes, int n_in,
                              void* d_out, int out_size)
{
    const float* xyz1     = (const float*)d_in[0];
    const float* xyz2     = (const float*)d_in[1];
    const float* points2  = (const float*)d_in[2];
    const float* points1  = (const float*)d_in[3];
    const float* pointsb1 = (const float*)d_in[4];
    const float* w0 = (const float*)d_in[5];
    const float* b0 = (const float*)d_in[6];
    const float* g0 = (const float*)d_in[7];
    const float* be0 = (const float*)d_in[8];
    const float* m0 = (const float*)d_in[9];
    const float* v0 = (const float*)d_in[10];
    const float* w1 = (const float*)d_in[11];
    const float* b1 = (const float*)d_in[12];
    const float* g1 = (const float*)d_in[13];
    const float* be1 = (const float*)d_in[14];
    const float* m1 = (const float*)d_in[15];
    const float* v1 = (const float*)d_in[16];
    float* out = (float*)d_out;

    const int smem_nn   = NN2 * 16;                        // 64 KB
    const int smem_main = (KIN * SX + 8192 + 32 * TN) * 4; // 140800 B
    cudaFuncSetAttribute(nn3_kernel, cudaFuncAttributeMaxDynamicSharedMemorySize, smem_nn);
    cudaFuncSetAttribute(fp_main_kernel, cudaFuncAttributeMaxDynamicSharedMemorySize, smem_main);

    fold_kernel<<<(MOUT * KIN + 255) / 256, 256>>>(w0, b0, g0, be0, m0, v0, 0);
    fold_kernel<<<(MOUT * MOUT + 255) / 256, 256>>>(w1, b1, g1, be1, m1, v1, 1);
    transpose_kernel<<<dim3(NN2 / 32, CC / 32, BB), dim3(32, 8)>>>(points2);
    nn3_kernel<<<(BB * NN1) / 256, 256, smem_nn>>>(xyz1, xyz2);
    fp_main_kernel<<<BB * (NN1 / TN), 256, smem_main>>>(points1, pointsb1, out);
}